// round 14
// baseline (speedup 1.0000x reference)
#include <cuda_runtime.h>
#include <cuda_fp16.h>
#include <math.h>
#include <stdint.h>

#define NN 50000
#define NE 625000
#define NGR 64
#define HC 128
#define FC 128
#define NGAUSS 50
#define KG 56                         // gaussian K padded to 56 (mult of 8)
#define NLAY 6
#define NT 128                        // node tile rows

#define NLUT 2048
#define DMAX 20.0f
#define LUT_STEP (DMAX / (float)NLUT)
#define INV_STEP ((float)NLUT / DMAX)

// smem strides
#define SA 60     // sD stride floats (lut_gen)
#define SB 132    // lut_gen weight/activation stride (floats)
#define SH2 68    // fused-kernel stride in half2 units

// ---------------- scratch (device globals; no allocation allowed) ----------
__device__ float g_v[NN * HC];
__device__ unsigned int g_xh0[NN * 64];           // x double buffer A (fp16x2)
__device__ unsigned int g_xh1[NN * 64];           // x double buffer B (fp16x2)
__device__ float g_W1t[NLAY * KG * FC];           // lut_gen: [l][k][n] tf32
__device__ float g_W2t[NLAY * FC * FC];           // lut_gen: [l][k][n] tf32
__device__ unsigned int g_lut_h[(size_t)NLAY * NLUT * 64]; // fp16x2 LUT rows
// node weights, fp16, TRANSPOSED [l][n][k] packed half2 (64 per row)
__device__ unsigned int g_hLin[NLAY * 128 * 64];
__device__ unsigned int g_hW1[NLAY * 128 * 64];
__device__ unsigned int g_hW2[NLAY * 128 * 64];
// CSR edge structure (by destination node)
__device__ float g_uraw[NE];
__device__ int   g_cnt[NN];
__device__ int   g_fill[NN];
__device__ int   g_rowstart[NN + 1];
__device__ uint2 g_e[NE];            // (src node, u bits), CSR order
// scan temporaries
#define SCB 256
#define SNB 196
__device__ int g_bsum[SNB];
__device__ int g_boff[SNB];

// ---------------- helpers ---------------------------------------------------
__device__ __forceinline__ uint32_t f2tf32(float x) {
    uint32_t r;
    asm("cvt.rna.tf32.f32 %0, %1;" : "=r"(r) : "f"(x));
    return r;
}
__device__ __forceinline__ void mma8(float* c, const uint32_t* a, uint32_t b0, uint32_t b1) {
    asm volatile("mma.sync.aligned.m16n8k8.row.col.f32.tf32.tf32.f32 "
                 "{%0,%1,%2,%3},{%4,%5,%6,%7},{%8,%9},{%0,%1,%2,%3};"
                 : "+f"(c[0]), "+f"(c[1]), "+f"(c[2]), "+f"(c[3])
                 : "r"(a[0]), "r"(a[1]), "r"(a[2]), "r"(a[3]), "r"(b0), "r"(b1));
}
__device__ __forceinline__ void mma16(float* c, const uint32_t* a, uint32_t b0, uint32_t b1) {
    asm volatile("mma.sync.aligned.m16n8k16.row.col.f32.f16.f16.f32 "
                 "{%0,%1,%2,%3},{%4,%5,%6,%7},{%8,%9},{%0,%1,%2,%3};"
                 : "+f"(c[0]), "+f"(c[1]), "+f"(c[2]), "+f"(c[3])
                 : "r"(a[0]), "r"(a[1]), "r"(a[2]), "r"(a[3]), "r"(b0), "r"(b1));
}
__device__ __forceinline__ float ssp_f(float x) {
    return fmaxf(x, 0.0f) + log1pf(expf(-fabsf(x))) - 0.69314718055994531f;
}
__device__ __forceinline__ float ssp_fast(float x) {
    return fmaxf(x, 0.0f) + __logf(1.0f + __expf(-fabsf(x))) - 0.69314718055994531f;
}

// ---------------- init: v = emb_table[z] + zero cnt/fill --------------------
__global__ void init_v_kernel(const int* __restrict__ z, const float* __restrict__ emb) {
    int idx = blockIdx.x * blockDim.x + threadIdx.x;
    if (idx < NN * HC) g_v[idx] = emb[z[idx >> 7] * HC + (idx & 127)];
    if (idx < NN) { g_cnt[idx] = 0; g_fill[idx] = 0; }
}

// ---------------- CSR build -------------------------------------------------
__global__ void edge_pre_kernel(const float* __restrict__ pos, const int* __restrict__ eidx) {
    int e = blockIdx.x * blockDim.x + threadIdx.x;
    if (e >= NE) return;
    int r = eidx[e], c = eidx[NE + e];
    float dx = pos[3 * r] - pos[3 * c];
    float dy = pos[3 * r + 1] - pos[3 * c + 1];
    float dz = pos[3 * r + 2] - pos[3 * c + 2];
    g_uraw[e] = sqrtf(dx * dx + dy * dy + dz * dz) * INV_STEP;
    atomicAdd(&g_cnt[c], 1);
}

__global__ void scan_part_kernel() {
    __shared__ int sh[SCB];
    int i = blockIdx.x * SCB + threadIdx.x;
    int v = (i < NN) ? g_cnt[i] : 0;
    sh[threadIdx.x] = v;
    __syncthreads();
    for (int off = SCB / 2; off; off >>= 1) {
        if (threadIdx.x < off) sh[threadIdx.x] += sh[threadIdx.x + off];
        __syncthreads();
    }
    if (threadIdx.x == 0) g_bsum[blockIdx.x] = sh[0];
}
__global__ void scan_top_kernel() {
    __shared__ int sh[256];
    int t = threadIdx.x;
    int v = (t < SNB) ? g_bsum[t] : 0;
    sh[t] = v;
    __syncthreads();
    for (int off = 1; off < 256; off <<= 1) {
        int u = (t >= off) ? sh[t - off] : 0;
        __syncthreads();
        sh[t] += u;
        __syncthreads();
    }
    if (t < SNB) g_boff[t] = sh[t] - v;
}
__global__ void scan_emit_kernel() {
    __shared__ int sh[SCB];
    int i = blockIdx.x * SCB + threadIdx.x;
    int v = (i < NN) ? g_cnt[i] : 0;
    sh[threadIdx.x] = v;
    __syncthreads();
    for (int off = 1; off < SCB; off <<= 1) {
        int u = (threadIdx.x >= off) ? sh[threadIdx.x - off] : 0;
        __syncthreads();
        sh[threadIdx.x] += u;
        __syncthreads();
    }
    if (i < NN) g_rowstart[i] = g_boff[blockIdx.x] + sh[threadIdx.x] - v;
    if (i == 0) g_rowstart[NN] = NE;
}

__global__ void scatter_kernel(const int* __restrict__ eidx) {
    int e = blockIdx.x * blockDim.x + threadIdx.x;
    if (e >= NE) return;
    int ci = eidx[NE + e];
    int pos = g_rowstart[ci] + atomicAdd(&g_fill[ci], 1);
    uint2 o;
    o.x = (unsigned int)eidx[e];
    o.y = __float_as_uint(g_uraw[e]);
    g_e[pos] = o;
}

// ---------------- prep: lut weights (tf32) + node weights fp16[n][k] --------
__global__ void prep_all_kernel(const float* __restrict__ mW1, const float* __restrict__ mW2,
                                const float* __restrict__ linW, const float* __restrict__ vW1,
                                const float* __restrict__ vW2) {
    int idx = blockIdx.x * blockDim.x + threadIdx.x;
    if (idx < NLAY * KG * FC) {
        int l = idx / (KG * FC), rem = idx % (KG * FC);
        int k = rem / FC, n = rem % FC;
        float v = (k < NGAUSS) ? mW1[(l * NGAUSS + k) * FC + n] : 0.0f;
        g_W1t[idx] = __uint_as_float(f2tf32(v));
    }
    if (idx < NLAY * FC * FC) {
        g_W2t[idx] = __uint_as_float(f2tf32(mW2[idx]));
    }
    if (idx < NLAY * 128 * 64) {
        int l = idx >> 13, rem = idx & 8191;
        int n = rem >> 6, c2 = rem & 63;
        int k = 2 * c2;
        size_t off = (size_t)l * 16384;
        const float* base = linW + off;
        __half2 h = __floats2half2_rn(base[k * 128 + n], base[(k + 1) * 128 + n]);
        g_hLin[idx] = *(unsigned int*)&h;
        base = vW1 + off;
        h = __floats2half2_rn(base[k * 128 + n], base[(k + 1) * 128 + n]);
        g_hW1[idx] = *(unsigned int*)&h;
        base = vW2 + off;
        h = __floats2half2_rn(base[k * 128 + n], base[(k + 1) * 128 + n]);
        g_hW2[idx] = *(unsigned int*)&h;
    }
}

__global__ void zero_out_kernel(float* __restrict__ out) {
    if (threadIdx.x < NGR) out[threadIdx.x] = 0.0f;
}

// ---------------- LUT generation (tf32 mma) ---------------------------------
#define OFF_SW1 0
#define OFF_SW2 (OFF_SW1 + KG * SB)
#define OFF_SD  (OFF_SW2 + FC * SB)
#define OFF_STT (OFF_SD + 128 * SA)
#define OFF_SB1 (OFF_STT + 128 * SB)
#define OFF_SB2 (OFF_SB1 + FC)
#define LUT_SMEM_F (OFF_SB2 + FC)

__global__ void __launch_bounds__(256, 1)
lut_gen_kernel(const float* __restrict__ mb1, const float* __restrict__ mb2)
{
    extern __shared__ float s[];
    float* sW1 = s + OFF_SW1;
    float* sW2 = s + OFF_SW2;
    float* sD  = s + OFF_SD;
    float* sT  = s + OFF_STT;
    float* sB1 = s + OFF_SB1;
    float* sB2 = s + OFF_SB2;

    int tid = threadIdx.x;
    int wid = tid >> 5, lane = tid & 31;
    int g = lane >> 2, r = lane & 3;
    int wm = wid & 3, wn = wid >> 2;
    int t = blockIdx.x;
    int l = blockIdx.y;

    {
        const float* w1 = g_W1t + (size_t)l * KG * FC;
        const float* w2 = g_W2t + (size_t)l * FC * FC;
        const float* b1 = mb1 + (size_t)l * FC;
        const float* b2 = mb2 + (size_t)l * FC;
        for (int i = tid; i < KG * FC; i += 256) sW1[(i >> 7) * SB + (i & 127)] = w1[i];
        for (int i = tid; i < FC * FC; i += 256) sW2[(i >> 7) * SB + (i & 127)] = w2[i];
        for (int i = tid; i < FC; i += 256) { sB1[i] = b1[i]; sB2[i] = b2[i]; }
    }
    {
        const float delta = 10.0f / 49.0f;
        const float coeff = -0.5f / (delta * delta);
        for (int i = tid; i < 128 * KG; i += 256) {
            int row = i / KG, k = i - row * KG;
            float d = (float)(t * 128 + row) * LUT_STEP;
            float dd = d - (float)k * delta;
            float v = (k < NGAUSS) ? expf(coeff * dd * dd) : 0.0f;
            sD[row * SA + k] = __uint_as_float(f2tf32(v));
        }
    }
    __syncthreads();

    float c1[2][8][4];
    #pragma unroll
    for (int im = 0; im < 2; im++)
        #pragma unroll
        for (int jn = 0; jn < 8; jn++)
            #pragma unroll
            for (int q = 0; q < 4; q++) c1[im][jn][q] = 0.0f;

    #pragma unroll
    for (int kk = 0; kk < KG / 8; kk++) {
        uint32_t a[2][4];
        #pragma unroll
        for (int im = 0; im < 2; im++) {
            int rb = wm * 32 + im * 16 + g;
            int kb = kk * 8 + r;
            a[im][0] = __float_as_uint(sD[rb * SA + kb]);
            a[im][1] = __float_as_uint(sD[(rb + 8) * SA + kb]);
            a[im][2] = __float_as_uint(sD[rb * SA + kb + 4]);
            a[im][3] = __float_as_uint(sD[(rb + 8) * SA + kb + 4]);
        }
        #pragma unroll
        for (int jn = 0; jn < 8; jn++) {
            int nb = wn * 64 + jn * 8 + g;
            uint32_t b0 = __float_as_uint(sW1[(kk * 8 + r) * SB + nb]);
            uint32_t bv = __float_as_uint(sW1[(kk * 8 + 4 + r) * SB + nb]);
            mma8(c1[0][jn], a[0], b0, bv);
            mma8(c1[1][jn], a[1], b0, bv);
        }
    }

    #pragma unroll
    for (int im = 0; im < 2; im++) {
        int rb = wm * 32 + im * 16 + g;
        #pragma unroll
        for (int jn = 0; jn < 8; jn++) {
            int col = wn * 64 + jn * 8 + 2 * r;
            float bb0 = sB1[col], bb1 = sB1[col + 1];
            float2 lo, hi;
            lo.x = __uint_as_float(f2tf32(ssp_f(c1[im][jn][0] + bb0)));
            lo.y = __uint_as_float(f2tf32(ssp_f(c1[im][jn][1] + bb1)));
            hi.x = __uint_as_float(f2tf32(ssp_f(c1[im][jn][2] + bb0)));
            hi.y = __uint_as_float(f2tf32(ssp_f(c1[im][jn][3] + bb1)));
            *(float2*)(sT + rb * SB + col) = lo;
            *(float2*)(sT + (rb + 8) * SB + col) = hi;
        }
    }
    __syncthreads();

    float c2[2][8][4];
    #pragma unroll
    for (int im = 0; im < 2; im++)
        #pragma unroll
        for (int jn = 0; jn < 8; jn++)
            #pragma unroll
            for (int q = 0; q < 4; q++) c2[im][jn][q] = 0.0f;

    #pragma unroll 4
    for (int kk = 0; kk < FC / 8; kk++) {
        uint32_t a[2][4];
        #pragma unroll
        for (int im = 0; im < 2; im++) {
            int rb = wm * 32 + im * 16 + g;
            int kb = kk * 8 + r;
            a[im][0] = __float_as_uint(sT[rb * SB + kb]);
            a[im][1] = __float_as_uint(sT[(rb + 8) * SB + kb]);
            a[im][2] = __float_as_uint(sT[rb * SB + kb + 4]);
            a[im][3] = __float_as_uint(sT[(rb + 8) * SB + kb + 4]);
        }
        #pragma unroll
        for (int jn = 0; jn < 8; jn++) {
            int nb = wn * 64 + jn * 8 + g;
            uint32_t b0 = __float_as_uint(sW2[(kk * 8 + r) * SB + nb]);
            uint32_t bv = __float_as_uint(sW2[(kk * 8 + 4 + r) * SB + nb]);
            mma8(c2[0][jn], a[0], b0, bv);
            mma8(c2[1][jn], a[1], b0, bv);
        }
    }

    unsigned int* lutL = g_lut_h + (size_t)l * NLUT * 64;
    #pragma unroll
    for (int q = 0; q < 4; q++) {
        int im = q >> 1, hi = q & 1;
        int row = wm * 32 + im * 16 + hi * 8 + g;
        int idx = t * 128 + row;
        float d = (float)idx * LUT_STEP;
        float Ce = 0.5f * (cosf(d * 0.31415926535897931f) + 1.0f);
        unsigned int* lp = lutL + (size_t)idx * 64;
        #pragma unroll
        for (int jn = 0; jn < 8; jn++) {
            int col = wn * 64 + jn * 8 + 2 * r;
            float ox = (c2[im][jn][hi * 2 + 0] + sB2[col]) * Ce;
            float oy = (c2[im][jn][hi * 2 + 1] + sB2[col + 1]) * Ce;
            __half2 h = __floats2half2_rn(ox, oy);
            lp[col >> 1] = *(unsigned int*)&h;
        }
    }
}

// ---------------- fused per-layer kernel: gather + 3 GEMMs ------------------
// full=1: sA = fp16(gather(lut, xin)) ; v += ssp(sA@W1+b1)@W2+b2 ; xout = fp16(v@lin)
// full=0: xout = fp16(g_v @ lin) only
#define FUS_U_W 0
#define FUS_U_A (128 * SH2)
#define FUS_U_H (2 * 128 * SH2)
#define FUS_U_B (3 * 128 * SH2)
#define FUSED_SMEM_B ((FUS_U_B + 256) * 4)

__global__ void __launch_bounds__(512, 2)
layer_fused_kernel(const unsigned int* __restrict__ W1h, const float* __restrict__ b1,
                   const unsigned int* __restrict__ W2h, const float* __restrict__ b2,
                   const unsigned int* __restrict__ linWh,
                   const unsigned int* __restrict__ lut,
                   const unsigned int* __restrict__ xin,
                   unsigned int* __restrict__ xout, int full)
{
    extern __shared__ unsigned int su[];
    unsigned int* sW = su + FUS_U_W;
    unsigned int* sA = su + FUS_U_A;
    unsigned int* sH = su + FUS_U_H;
    float* sB1 = (float*)(su + FUS_U_B);
    float* sB2 = sB1 + 128;

    int tid = threadIdx.x;
    int wid = tid >> 5, lane = tid & 31;
    int g = lane >> 2, r = lane & 3;
    int wm = wid & 3, wn = wid >> 2;   // 4x4 warp grid, 32x32 tiles
    int n0 = blockIdx.x * NT;

    float c[2][4][4];

    if (full) {
        // stage W1 + biases
        for (int i = tid; i < 128 * 64; i += 512)
            sW[(i >> 6) * SH2 + (i & 63)] = W1h[i];
        if (tid < FC) sB1[tid] = b1[tid];
        else if (tid >= 128 && tid < 256) sB2[tid - 128] = b2[tid - 128];

        // gather phase: warp per node, 8 nodes per warp -> sA (fp16)
        #pragma unroll 1
        for (int nd = wid; nd < NT; nd += 16) {
            int n = n0 + nd;
            float4 acc = make_float4(0.0f, 0.0f, 0.0f, 0.0f);
            if (n < NN) {
                int s = g_rowstart[n], e = g_rowstart[n + 1];
                #pragma unroll 4
                for (int k = s; k < e; k++) {
                    uint2 ed = g_e[k];
                    int rj = (int)ed.x;
                    float u = __uint_as_float(ed.y);
                    int i0 = (int)u;
                    i0 = (i0 > NLUT - 2) ? (NLUT - 2) : i0;
                    float f = u - (float)i0;
                    const uint2* la = (const uint2*)(lut + (size_t)i0 * 64) + lane;
                    uint2 A = la[0];
                    uint2 B = la[32];
                    uint2 X = ((const uint2*)(xin + (size_t)rj * 64))[lane];
                    float2 a0 = __half22float2(*(__half2*)&A.x);
                    float2 a1 = __half22float2(*(__half2*)&A.y);
                    float2 b0 = __half22float2(*(__half2*)&B.x);
                    float2 b1v = __half22float2(*(__half2*)&B.y);
                    float2 x0 = __half22float2(*(__half2*)&X.x);
                    float2 x1 = __half22float2(*(__half2*)&X.y);
                    acc.x = fmaf(fmaf(f, b0.x - a0.x, a0.x), x0.x, acc.x);
                    acc.y = fmaf(fmaf(f, b0.y - a0.y, a0.y), x0.y, acc.y);
                    acc.z = fmaf(fmaf(f, b1v.x - a1.x, a1.x), x1.x, acc.z);
                    acc.w = fmaf(fmaf(f, b1v.y - a1.y, a1.y), x1.y, acc.w);
                }
            }
            __half2 h0 = __floats2half2_rn(acc.x, acc.y);
            __half2 h1 = __floats2half2_rn(acc.z, acc.w);
            sA[nd * SH2 + 2 * lane] = *(unsigned int*)&h0;
            sA[nd * SH2 + 2 * lane + 1] = *(unsigned int*)&h1;
        }
        __syncthreads();

        // GEMM A: h = ssp(agg @ W1 + b1)
        #pragma unroll
        for (int im = 0; im < 2; im++)
            #pragma unroll
            for (int jn = 0; jn < 4; jn++)
                #pragma unroll
                for (int q = 0; q < 4; q++) c[im][jn][q] = 0.0f;
        #pragma unroll
        for (int kk = 0; kk < 8; kk++) {
            uint32_t a[2][4];
            #pragma unroll
            for (int im = 0; im < 2; im++) {
                int rb = wm * 32 + im * 16 + g;
                a[im][0] = sA[rb * SH2 + kk * 8 + r];
                a[im][1] = sA[(rb + 8) * SH2 + kk * 8 + r];
                a[im][2] = sA[rb * SH2 + kk * 8 + 4 + r];
                a[im][3] = sA[(rb + 8) * SH2 + kk * 8 + 4 + r];
            }
            #pragma unroll
            for (int jn = 0; jn < 4; jn++) {
                int nb = wn * 32 + jn * 8 + g;
                uint32_t b0 = sW[nb * SH2 + kk * 8 + r];
                uint32_t bv = sW[nb * SH2 + kk * 8 + 4 + r];
                mma16(c[0][jn], a[0], b0, bv);
                mma16(c[1][jn], a[1], b0, bv);
            }
        }
        #pragma unroll
        for (int q = 0; q < 4; q++) {
            int im = q >> 1, hi = q & 1;
            int row = wm * 32 + im * 16 + hi * 8 + g;
            #pragma unroll
            for (int jn = 0; jn < 4; jn++) {
                int col = wn * 32 + jn * 8 + 2 * r;
                __half2 h = __floats2half2_rn(ssp_fast(c[im][jn][hi * 2 + 0] + sB1[col]),
                                              ssp_fast(c[im][jn][hi * 2 + 1] + sB1[col + 1]));
                sH[row * SH2 + (col >> 1)] = *(unsigned int*)&h;
            }
        }
        __syncthreads();
        for (int i = tid; i < 128 * 64; i += 512)
            sW[(i >> 6) * SH2 + (i & 63)] = W2h[i];
        __syncthreads();

        // GEMM B: v += h @ W2 + b2 ; sA = fp16(v_new)
        #pragma unroll
        for (int im = 0; im < 2; im++)
            #pragma unroll
            for (int jn = 0; jn < 4; jn++)
                #pragma unroll
                for (int q = 0; q < 4; q++) c[im][jn][q] = 0.0f;
        #pragma unroll
        for (int kk = 0; kk < 8; kk++) {
            uint32_t a[2][4];
            #pragma unroll
            for (int im = 0; im < 2; im++) {
                int rb = wm * 32 + im * 16 + g;
                a[im][0] = sH[rb * SH2 + kk * 8 + r];
                a[im][1] = sH[(rb + 8) * SH2 + kk * 8 + r];
                a[im][2] = sH[rb * SH2 + kk * 8 + 4 + r];
                a[im][3] = sH[(rb + 8) * SH2 + kk * 8 + 4 + r];
            }
            #pragma unroll
            for (int jn = 0; jn < 4; jn++) {
                int nb = wn * 32 + jn * 8 + g;
                uint32_t b0 = sW[nb * SH2 + kk * 8 + r];
                uint32_t bv = sW[nb * SH2 + kk * 8 + 4 + r];
                mma16(c[0][jn], a[0], b0, bv);
                mma16(c[1][jn], a[1], b0, bv);
            }
        }
        #pragma unroll
        for (int q = 0; q < 4; q++) {
            int im = q >> 1, hi = q & 1;
            int row = wm * 32 + im * 16 + hi * 8 + g;
            int n = n0 + row;
            if (n >= NN) continue;
            float* vp = g_v + (size_t)n * HC;
            #pragma unroll
            for (int jn = 0; jn < 4; jn++) {
                int col = wn * 32 + jn * 8 + 2 * r;
                float2 old = *(const float2*)(vp + col);
                float2 o;
                o.x = old.x + c[im][jn][hi * 2 + 0] + sB2[col];
                o.y = old.y + c[im][jn][hi * 2 + 1] + sB2[col + 1];
                *(float2*)(vp + col) = o;
                __half2 h = __floats2half2_rn(o.x, o.y);
                sA[row * SH2 + (col >> 1)] = *(unsigned int*)&h;
            }
        }
        if (!linWh) return;
        __syncthreads();
    } else {
        for (int i = tid; i < 128 * 64; i += 512) {
            int row = i >> 6, c2 = i & 63;
            int n = n0 + row;
            float2 vv = (n < NN) ? *(const float2*)(g_v + (size_t)n * HC + 2 * c2)
                                 : make_float2(0.0f, 0.0f);
            __half2 h = __floats2half2_rn(vv.x, vv.y);
            sA[row * SH2 + c2] = *(unsigned int*)&h;
        }
    }

    // GEMM C: x = v_new @ lin -> fp16 to xout
    for (int i = tid; i < 128 * 64; i += 512)
        sW[(i >> 6) * SH2 + (i & 63)] = linWh[i];
    __syncthreads();

    #pragma unroll
    for (int im = 0; im < 2; im++)
        #pragma unroll
        for (int jn = 0; jn < 4; jn++)
            #pragma unroll
            for (int q = 0; q < 4; q++) c[im][jn][q] = 0.0f;
    #pragma unroll
    for (int kk = 0; kk < 8; kk++) {
        uint32_t a[2][4];
        #pragma unroll
        for (int im = 0; im < 2; im++) {
            int rb = wm * 32 + im * 16 + g;
            a[im][0] = sA[rb * SH2 + kk * 8 + r];
            a[im][1] = sA[(rb + 8) * SH2 + kk * 8 + r];
            a[im][2] = sA[rb * SH2 + kk * 8 + 4 + r];
            a[im][3] = sA[(rb + 8) * SH2 + kk * 8 + 4 + r];
        }
        #pragma unroll
        for (int jn = 0; jn < 4; jn++) {
            int nb = wn * 32 + jn * 8 + g;
            uint32_t b0 = sW[nb * SH2 + kk * 8 + r];
            uint32_t bv = sW[nb * SH2 + kk * 8 + 4 + r];
            mma16(c[0][jn], a[0], b0, bv);
            mma16(c[1][jn], a[1], b0, bv);
        }
    }
    #pragma unroll
    for (int q = 0; q < 4; q++) {
        int im = q >> 1, hi = q & 1;
        int row = wm * 32 + im * 16 + hi * 8 + g;
        int n = n0 + row;
        if (n >= NN) continue;
        unsigned int* xp = xout + (size_t)n * 64;
        #pragma unroll
        for (int jn = 0; jn < 4; jn++) {
            int col = wn * 32 + jn * 8 + 2 * r;
            __half2 h = __floats2half2_rn(c[im][jn][hi * 2 + 0], c[im][jn][hi * 2 + 1]);
            xp[col >> 1] = *(unsigned int*)&h;
        }
    }
}

// ---------------- readout ---------------------------------------------------
__global__ void readout_kernel(const int* __restrict__ batch,
                               const float* __restrict__ uW1, const float* __restrict__ ub1,
                               const float* __restrict__ uW2, const float* __restrict__ ub2,
                               float* __restrict__ out)
{
    __shared__ float sv[8][HC];
    int tid = threadIdx.x;
    int w = tid >> 5, l = tid & 31;
    int n0 = blockIdx.x * 8;
    for (int i = tid; i < 8 * HC; i += 256) {
        int n = n0 + (i >> 7);
        sv[i >> 7][i & 127] = (n < NN) ? g_v[(size_t)n * HC + (i & 127)] : 0.0f;
    }
    __syncthreads();
    int n = n0 + w;
    if (n >= NN) return;
    float a0 = 0.0f, a1 = 0.0f;
    #pragma unroll 8
    for (int h = 0; h < HC; h++) {
        float vv = sv[w][h];
        a0 += vv * uW1[h * 64 + l];
        a1 += vv * uW1[h * 64 + l + 32];
    }
    float h0 = ssp_f(a0 + ub1[l]);
    float h1 = ssp_f(a1 + ub1[l + 32]);
    float p = h0 * uW2[l] + h1 * uW2[l + 32];
    #pragma unroll
    for (int o = 16; o; o >>= 1) p += __shfl_down_sync(0xffffffffu, p, o);
    if (l == 0) atomicAdd(&out[batch[n]], p + ub2[0]);
}

// ---------------- launch ----------------------------------------------------
extern "C" void kernel_launch(void* const* d_in, const int* in_sizes, int n_in,
                              void* d_out, int out_size)
{
    const int*   z     = (const int*)d_in[0];
    const float* pos   = (const float*)d_in[1];
    const int*   batch = (const int*)d_in[2];
    const int*   eidx  = (const int*)d_in[3];
    const float* emb   = (const float*)d_in[4];
    const float* lin_W = (const float*)d_in[5];
    const float* mW1   = (const float*)d_in[6];
    const float* mb1   = (const float*)d_in[7];
    const float* mW2   = (const float*)d_in[8];
    const float* mb2   = (const float*)d_in[9];
    const float* vW1   = (const float*)d_in[10];
    const float* vb1   = (const float*)d_in[11];
    const float* vW2   = (const float*)d_in[12];
    const float* vb2   = (const float*)d_in[13];
    const float* uW1   = (const float*)d_in[14];
    const float* ub1   = (const float*)d_in[15];
    const float* uW2   = (const float*)d_in[16];
    const float* ub2   = (const float*)d_in[17];
    float* out = (float*)d_out;

    const int LUT_SMEM = LUT_SMEM_F * (int)sizeof(float);
    cudaFuncSetAttribute(lut_gen_kernel, cudaFuncAttributeMaxDynamicSharedMemorySize, LUT_SMEM);
    cudaFuncSetAttribute(layer_fused_kernel, cudaFuncAttributeMaxDynamicSharedMemorySize, FUSED_SMEM_B);

    init_v_kernel<<<(NN * HC + 255) / 256, 256>>>(z, emb);
    edge_pre_kernel<<<(NE + 255) / 256, 256>>>(pos, eidx);
    scan_part_kernel<<<SNB, SCB>>>();
    scan_top_kernel<<<1, 256>>>();
    scan_emit_kernel<<<SNB, SCB>>>();
    scatter_kernel<<<(NE + 255) / 256, 256>>>(eidx);
    prep_all_kernel<<<(NLAY * FC * FC + 255) / 256, 256>>>(mW1, mW2, lin_W, vW1, vW2);
    lut_gen_kernel<<<dim3(NLUT / 128, NLAY), 256, LUT_SMEM>>>(mb1, mb2);

    const int NODE_GRID = (NN + NT - 1) / NT;   // 391
    unsigned int* lutDev;
    cudaGetSymbolAddress((void**)&lutDev, g_lut_h);
    unsigned int *hLin, *hW1, *hW2, *xh0, *xh1;
    cudaGetSymbolAddress((void**)&hLin, g_hLin);
    cudaGetSymbolAddress((void**)&hW1, g_hW1);
    cudaGetSymbolAddress((void**)&hW2, g_hW2);
    cudaGetSymbolAddress((void**)&xh0, g_xh0);
    cudaGetSymbolAddress((void**)&xh1, g_xh1);

    // initial: x0 = v @ lin_W[0]  (writes buf0)
    layer_fused_kernel<<<NODE_GRID, 512, FUSED_SMEM_B>>>(
        nullptr, nullptr, nullptr, nullptr, hLin, nullptr, nullptr, xh0, 0);
    for (int l = 0; l < NLAY; l++) {
        const unsigned int* nextLin = (l + 1 < NLAY) ? (hLin + (size_t)(l + 1) * 8192) : nullptr;
        unsigned int* xin  = (l & 1) ? xh1 : xh0;
        unsigned int* xout = (l & 1) ? xh0 : xh1;
        layer_fused_kernel<<<NODE_GRID, 512, FUSED_SMEM_B>>>(
            hW1 + (size_t)l * 8192, vb1 + (size_t)l * HC,
            hW2 + (size_t)l * 8192, vb2 + (size_t)l * HC,
            nextLin, lutDev + (size_t)l * NLUT * 64, xin, xout, 1);
    }

    zero_out_kernel<<<1, 64>>>(out);
    readout_kernel<<<(NN + 7) / 8, 256>>>(batch, uW1, ub1, uW2, ub2, out);
    (void)in_sizes; (void)n_in; (void)out_size;
}

// round 15
// speedup vs baseline: 1.0116x; 1.0116x over previous
#include <cuda_runtime.h>
#include <cuda_fp16.h>
#include <math.h>
#include <stdint.h>

#define NN 50000
#define NE 625000
#define NGR 64
#define HC 128
#define FC 128
#define NGAUSS 50
#define KG 56
#define NLAY 6
#define NT 128

#define NLUT 2048
#define DMAX 20.0f
#define LUT_STEP (DMAX / (float)NLUT)
#define INV_STEP ((float)NLUT / DMAX)

#define SA 60     // lut_gen sD stride (floats)
#define SB 132    // lut_gen weight stride (floats)
#define SH2 68    // fused stride in half2 units (272 bytes/row)

// ---------------- scratch ---------------------------------------------------
__device__ float g_v[NN * HC];
__device__ unsigned int g_xh0[NN * 64];
__device__ unsigned int g_xh1[NN * 64];
__device__ unsigned int g_lut_h[(size_t)NLAY * NLUT * 64];
__device__ unsigned int g_hLin[NLAY * 128 * 64];
__device__ unsigned int g_hW1[NLAY * 128 * 64];
__device__ unsigned int g_hW2[NLAY * 128 * 64];
__device__ float g_uraw[NE];
__device__ int   g_cnt[NN];
__device__ int   g_fill[NN];
__device__ int   g_rowstart[NN + 1];
__device__ uint2 g_e[NE];
#define SCB 256
#define SNB 196
__device__ int g_bsum[SNB];

// ---------------- helpers ---------------------------------------------------
__device__ __forceinline__ uint32_t smem_u32(const void* p) {
    uint32_t a;
    asm("{ .reg .u64 t; cvta.to.shared.u64 t, %1; cvt.u32.u64 %0, t; }" : "=r"(a) : "l"(p));
    return a;
}
__device__ __forceinline__ uint32_t f2tf32(float x) {
    uint32_t r;
    asm("cvt.rna.tf32.f32 %0, %1;" : "=r"(r) : "f"(x));
    return r;
}
__device__ __forceinline__ void mma8(float* c, const uint32_t* a, uint32_t b0, uint32_t b1) {
    asm volatile("mma.sync.aligned.m16n8k8.row.col.f32.tf32.tf32.f32 "
                 "{%0,%1,%2,%3},{%4,%5,%6,%7},{%8,%9},{%0,%1,%2,%3};"
                 : "+f"(c[0]), "+f"(c[1]), "+f"(c[2]), "+f"(c[3])
                 : "r"(a[0]), "r"(a[1]), "r"(a[2]), "r"(a[3]), "r"(b0), "r"(b1));
}
__device__ __forceinline__ void mma16(float* c, const uint32_t* a, uint32_t b0, uint32_t b1) {
    asm volatile("mma.sync.aligned.m16n8k16.row.col.f32.f16.f16.f32 "
                 "{%0,%1,%2,%3},{%4,%5,%6,%7},{%8,%9},{%0,%1,%2,%3};"
                 : "+f"(c[0]), "+f"(c[1]), "+f"(c[2]), "+f"(c[3])
                 : "r"(a[0]), "r"(a[1]), "r"(a[2]), "r"(a[3]), "r"(b0), "r"(b1));
}
__device__ __forceinline__ void ldsm_x4(uint32_t* d, uint32_t addr) {
    asm volatile("ldmatrix.sync.aligned.m8n8.x4.shared.b16 {%0,%1,%2,%3}, [%4];"
                 : "=r"(d[0]), "=r"(d[1]), "=r"(d[2]), "=r"(d[3]) : "r"(addr));
}
__device__ __forceinline__ void ldsm_x2(uint32_t* d, uint32_t addr) {
    asm volatile("ldmatrix.sync.aligned.m8n8.x2.shared.b16 {%0,%1}, [%2];"
                 : "=r"(d[0]), "=r"(d[1]) : "r"(addr));
}
__device__ __forceinline__ float ssp_f(float x) {
    return fmaxf(x, 0.0f) + log1pf(expf(-fabsf(x))) - 0.69314718055994531f;
}
__device__ __forceinline__ float ssp_fast(float x) {
    return fmaxf(x, 0.0f) + __logf(1.0f + __expf(-fabsf(x))) - 0.69314718055994531f;
}

// ---------------- init ------------------------------------------------------
__global__ void init_v_kernel(const int* __restrict__ z, const float* __restrict__ emb) {
    int idx = blockIdx.x * blockDim.x + threadIdx.x;
    if (idx < NN * HC) g_v[idx] = emb[z[idx >> 7] * HC + (idx & 127)];
    if (idx < NN) { g_cnt[idx] = 0; g_fill[idx] = 0; }
}

// ---------------- CSR build -------------------------------------------------
__global__ void edge_pre_kernel(const float* __restrict__ pos, const int* __restrict__ eidx) {
    int e = blockIdx.x * blockDim.x + threadIdx.x;
    if (e >= NE) return;
    int r = eidx[e], c = eidx[NE + e];
    float dx = pos[3 * r] - pos[3 * c];
    float dy = pos[3 * r + 1] - pos[3 * c + 1];
    float dz = pos[3 * r + 2] - pos[3 * c + 2];
    g_uraw[e] = sqrtf(dx * dx + dy * dy + dz * dz) * INV_STEP;
    atomicAdd(&g_cnt[c], 1);
}

__global__ void scan_part_kernel() {
    __shared__ int sh[SCB];
    int i = blockIdx.x * SCB + threadIdx.x;
    int v = (i < NN) ? g_cnt[i] : 0;
    sh[threadIdx.x] = v;
    __syncthreads();
    for (int off = SCB / 2; off; off >>= 1) {
        if (threadIdx.x < off) sh[threadIdx.x] += sh[threadIdx.x + off];
        __syncthreads();
    }
    if (threadIdx.x == 0) g_bsum[blockIdx.x] = sh[0];
}
// merged top-level + per-block emit
__global__ void scan_emit_kernel() {
    __shared__ int sh[SCB];
    int pre = 0;
    for (int j = threadIdx.x; j < blockIdx.x; j += SCB) pre += g_bsum[j];
    sh[threadIdx.x] = pre;
    __syncthreads();
    for (int off = SCB / 2; off; off >>= 1) {
        if (threadIdx.x < off) sh[threadIdx.x] += sh[threadIdx.x + off];
        __syncthreads();
    }
    int base = sh[0];
    __syncthreads();
    int i = blockIdx.x * SCB + threadIdx.x;
    int v = (i < NN) ? g_cnt[i] : 0;
    sh[threadIdx.x] = v;
    __syncthreads();
    for (int off = 1; off < SCB; off <<= 1) {
        int u = (threadIdx.x >= off) ? sh[threadIdx.x - off] : 0;
        __syncthreads();
        sh[threadIdx.x] += u;
        __syncthreads();
    }
    if (i < NN) g_rowstart[i] = base + sh[threadIdx.x] - v;
    if (i == 0) g_rowstart[NN] = NE;
}

__global__ void scatter_kernel(const int* __restrict__ eidx) {
    int e = blockIdx.x * blockDim.x + threadIdx.x;
    if (e >= NE) return;
    int ci = eidx[NE + e];
    int pos = g_rowstart[ci] + atomicAdd(&g_fill[ci], 1);
    uint2 o;
    o.x = (unsigned int)eidx[e];
    o.y = __float_as_uint(g_uraw[e]);
    g_e[pos] = o;
}

// ---------------- prep: node weights fp16 [l][n][k] -------------------------
__global__ void prep_wh_kernel(const float* __restrict__ linW,
                               const float* __restrict__ vW1,
                               const float* __restrict__ vW2) {
    int idx = blockIdx.x * blockDim.x + threadIdx.x;
    if (idx >= NLAY * 128 * 64) return;
    int l = idx >> 13, rem = idx & 8191;
    int n = rem >> 6, c2 = rem & 63;
    int k = 2 * c2;
    size_t off = (size_t)l * 16384;
    const float* base = linW + off;
    __half2 h = __floats2half2_rn(base[k * 128 + n], base[(k + 1) * 128 + n]);
    g_hLin[idx] = *(unsigned int*)&h;
    base = vW1 + off;
    h = __floats2half2_rn(base[k * 128 + n], base[(k + 1) * 128 + n]);
    g_hW1[idx] = *(unsigned int*)&h;
    base = vW2 + off;
    h = __floats2half2_rn(base[k * 128 + n], base[(k + 1) * 128 + n]);
    g_hW2[idx] = *(unsigned int*)&h;
}

__global__ void zero_out_kernel(float* __restrict__ out) {
    if (threadIdx.x < NGR) out[threadIdx.x] = 0.0f;
}

// ---------------- LUT generation (tf32 mma; weights staged inline) ----------
#define OFF_SW1 0
#define OFF_SW2 (OFF_SW1 + KG * SB)
#define OFF_SD  (OFF_SW2 + FC * SB)
#define OFF_STT (OFF_SD + 128 * SA)
#define OFF_SB1 (OFF_STT + 128 * SB)
#define OFF_SB2 (OFF_SB1 + FC)
#define LUT_SMEM_F (OFF_SB2 + FC)

__global__ void __launch_bounds__(256, 1)
lut_gen_kernel(const float* __restrict__ mW1, const float* __restrict__ mW2,
               const float* __restrict__ mb1, const float* __restrict__ mb2)
{
    extern __shared__ float s[];
    float* sW1 = s + OFF_SW1;
    float* sW2 = s + OFF_SW2;
    float* sD  = s + OFF_SD;
    float* sT  = s + OFF_STT;
    float* sB1 = s + OFF_SB1;
    float* sB2 = s + OFF_SB2;

    int tid = threadIdx.x;
    int wid = tid >> 5, lane = tid & 31;
    int g = lane >> 2, r = lane & 3;
    int wm = wid & 3, wn = wid >> 2;
    int t = blockIdx.x;
    int l = blockIdx.y;

    {
        const float* w1 = mW1 + (size_t)l * NGAUSS * FC;
        const float* w2 = mW2 + (size_t)l * FC * FC;
        const float* b1 = mb1 + (size_t)l * FC;
        const float* b2 = mb2 + (size_t)l * FC;
        for (int i = tid; i < KG * FC; i += 256) {
            int k = i >> 7, n = i & 127;
            float v = (k < NGAUSS) ? w1[k * FC + n] : 0.0f;
            sW1[k * SB + n] = __uint_as_float(f2tf32(v));
        }
        for (int i = tid; i < FC * FC; i += 256)
            sW2[(i >> 7) * SB + (i & 127)] = __uint_as_float(f2tf32(w2[i]));
        for (int i = tid; i < FC; i += 256) { sB1[i] = b1[i]; sB2[i] = b2[i]; }
    }
    {
        const float delta = 10.0f / 49.0f;
        const float coeff = -0.5f / (delta * delta);
        for (int i = tid; i < 128 * KG; i += 256) {
            int row = i / KG, k = i - row * KG;
            float d = (float)(t * 128 + row) * LUT_STEP;
            float dd = d - (float)k * delta;
            float v = (k < NGAUSS) ? expf(coeff * dd * dd) : 0.0f;
            sD[row * SA + k] = __uint_as_float(f2tf32(v));
        }
    }
    __syncthreads();

    float c1[2][8][4];
    #pragma unroll
    for (int im = 0; im < 2; im++)
        #pragma unroll
        for (int jn = 0; jn < 8; jn++)
            #pragma unroll
            for (int q = 0; q < 4; q++) c1[im][jn][q] = 0.0f;

    #pragma unroll
    for (int kk = 0; kk < KG / 8; kk++) {
        uint32_t a[2][4];
        #pragma unroll
        for (int im = 0; im < 2; im++) {
            int rb = wm * 32 + im * 16 + g;
            int kb = kk * 8 + r;
            a[im][0] = __float_as_uint(sD[rb * SA + kb]);
            a[im][1] = __float_as_uint(sD[(rb + 8) * SA + kb]);
            a[im][2] = __float_as_uint(sD[rb * SA + kb + 4]);
            a[im][3] = __float_as_uint(sD[(rb + 8) * SA + kb + 4]);
        }
        #pragma unroll
        for (int jn = 0; jn < 8; jn++) {
            int nb = wn * 64 + jn * 8 + g;
            uint32_t b0 = __float_as_uint(sW1[(kk * 8 + r) * SB + nb]);
            uint32_t bv = __float_as_uint(sW1[(kk * 8 + 4 + r) * SB + nb]);
            mma8(c1[0][jn], a[0], b0, bv);
            mma8(c1[1][jn], a[1], b0, bv);
        }
    }

    #pragma unroll
    for (int im = 0; im < 2; im++) {
        int rb = wm * 32 + im * 16 + g;
        #pragma unroll
        for (int jn = 0; jn < 8; jn++) {
            int col = wn * 64 + jn * 8 + 2 * r;
            float bb0 = sB1[col], bb1 = sB1[col + 1];
            float2 lo, hi;
            lo.x = __uint_as_float(f2tf32(ssp_f(c1[im][jn][0] + bb0)));
            lo.y = __uint_as_float(f2tf32(ssp_f(c1[im][jn][1] + bb1)));
            hi.x = __uint_as_float(f2tf32(ssp_f(c1[im][jn][2] + bb0)));
            hi.y = __uint_as_float(f2tf32(ssp_f(c1[im][jn][3] + bb1)));
            *(float2*)(sT + rb * SB + col) = lo;
            *(float2*)(sT + (rb + 8) * SB + col) = hi;
        }
    }
    __syncthreads();

    float c2[2][8][4];
    #pragma unroll
    for (int im = 0; im < 2; im++)
        #pragma unroll
        for (int jn = 0; jn < 8; jn++)
            #pragma unroll
            for (int q = 0; q < 4; q++) c2[im][jn][q] = 0.0f;

    #pragma unroll 4
    for (int kk = 0; kk < FC / 8; kk++) {
        uint32_t a[2][4];
        #pragma unroll
        for (int im = 0; im < 2; im++) {
            int rb = wm * 32 + im * 16 + g;
            int kb = kk * 8 + r;
            a[im][0] = __float_as_uint(sT[rb * SB + kb]);
            a[im][1] = __float_as_uint(sT[(rb + 8) * SB + kb]);
            a[im][2] = __float_as_uint(sT[rb * SB + kb + 4]);
            a[im][3] = __float_as_uint(sT[(rb + 8) * SB + kb + 4]);
        }
        #pragma unroll
        for (int jn = 0; jn < 8; jn++) {
            int nb = wn * 64 + jn * 8 + g;
            uint32_t b0 = __float_as_uint(sW2[(kk * 8 + r) * SB + nb]);
            uint32_t bv = __float_as_uint(sW2[(kk * 8 + 4 + r) * SB + nb]);
            mma8(c2[0][jn], a[0], b0, bv);
            mma8(c2[1][jn], a[1], b0, bv);
        }
    }

    unsigned int* lutL = g_lut_h + (size_t)l * NLUT * 64;
    #pragma unroll
    for (int q = 0; q < 4; q++) {
        int im = q >> 1, hi = q & 1;
        int row = wm * 32 + im * 16 + hi * 8 + g;
        int idx = t * 128 + row;
        float d = (float)idx * LUT_STEP;
        float Ce = 0.5f * (cosf(d * 0.31415926535897931f) + 1.0f);
        unsigned int* lp = lutL + (size_t)idx * 64;
        #pragma unroll
        for (int jn = 0; jn < 8; jn++) {
            int col = wn * 64 + jn * 8 + 2 * r;
            float ox = (c2[im][jn][hi * 2 + 0] + sB2[col]) * Ce;
            float oy = (c2[im][jn][hi * 2 + 1] + sB2[col + 1]) * Ce;
            __half2 h = __floats2half2_rn(ox, oy);
            lp[col >> 1] = *(unsigned int*)&h;
        }
    }
}

// ---------------- fused per-layer kernel: gather + 3 GEMMs (ldmatrix) -------
#define FUS_U_W 0
#define FUS_U_A (128 * SH2)
#define FUS_U_H (2 * 128 * SH2)
#define FUS_U_B (3 * 128 * SH2)
#define FUSED_SMEM_B ((FUS_U_B + 256) * 4)

// one GEMM inner loop via ldmatrix; A region byte addr aA (incl lane offset), B bB
#define GEMM_LDSM(cacc, aA, bB)                                              \
    do {                                                                     \
        _Pragma("unroll")                                                    \
        for (int kk = 0; kk < 8; kk++) {                                     \
            uint32_t a0[4], a1[4], f0[2], f1[2], f2[2], f3[2];               \
            ldsm_x4(a0, (aA) + kk * 32);                                     \
            ldsm_x4(a1, (aA) + 4352 + kk * 32);                              \
            ldsm_x2(f0, (bB) + kk * 32);                                     \
            ldsm_x2(f1, (bB) + 2176 + kk * 32);                              \
            ldsm_x2(f2, (bB) + 4352 + kk * 32);                              \
            ldsm_x2(f3, (bB) + 6528 + kk * 32);                              \
            mma16(cacc[0][0], a0, f0[0], f0[1]);                             \
            mma16(cacc[1][0], a1, f0[0], f0[1]);                             \
            mma16(cacc[0][1], a0, f1[0], f1[1]);                             \
            mma16(cacc[1][1], a1, f1[0], f1[1]);                             \
            mma16(cacc[0][2], a0, f2[0], f2[1]);                             \
            mma16(cacc[1][2], a1, f2[0], f2[1]);                             \
            mma16(cacc[0][3], a0, f3[0], f3[1]);                             \
            mma16(cacc[1][3], a1, f3[0], f3[1]);                             \
        }                                                                    \
    } while (0)

__global__ void __launch_bounds__(512, 2)
layer_fused_kernel(const unsigned int* __restrict__ W1h, const float* __restrict__ b1,
                   const unsigned int* __restrict__ W2h, const float* __restrict__ b2,
                   const unsigned int* __restrict__ linWh,
                   const unsigned int* __restrict__ lut,
                   const unsigned int* __restrict__ xin,
                   unsigned int* __restrict__ xout, int full)
{
    extern __shared__ unsigned int su[];
    unsigned int* sW = su + FUS_U_W;
    unsigned int* sA = su + FUS_U_A;
    unsigned int* sH = su + FUS_U_H;
    float* sB1 = (float*)(su + FUS_U_B);
    float* sB2 = sB1 + 128;

    int tid = threadIdx.x;
    int wid = tid >> 5, lane = tid & 31;
    int g = lane >> 2, r = lane & 3;
    int wm = wid & 3, wn = wid >> 2;   // 4x4 warp grid, 32x32 tiles
    int n0 = blockIdx.x * NT;

    // ldmatrix lane address offsets (bytes) within a [128][SH2] region
    uint32_t sb = smem_u32(su);
    int t4 = lane >> 3, r8 = lane & 7;
    uint32_t aoff = (uint32_t)((wm * 32 + (t4 & 1) * 8 + r8) * 272 + (t4 >> 1) * 16);
    uint32_t boff = (uint32_t)((wn * 32 + r8) * 272 + ((lane >> 3) & 1) * 16);
    uint32_t bB = sb + boff;                 // B always from sW (region offset 0)
    uint32_t aRegA = sb + FUS_U_A * 4 + aoff;
    uint32_t aRegH = sb + FUS_U_H * 4 + aoff;

    float c[2][4][4];

    if (full) {
        for (int i = tid; i < 128 * 64; i += 512)
            sW[(i >> 6) * SH2 + (i & 63)] = W1h[i];
        if (tid < FC) sB1[tid] = b1[tid];
        else if (tid >= 128 && tid < 256) sB2[tid - 128] = b2[tid - 128];

        // gather: warp per node, 8 nodes per warp -> sA (fp16)
        #pragma unroll 1
        for (int nd = wid; nd < NT; nd += 16) {
            int n = n0 + nd;
            float4 acc = make_float4(0.0f, 0.0f, 0.0f, 0.0f);
            if (n < NN) {
                int s = g_rowstart[n], e = g_rowstart[n + 1];
                #pragma unroll 4
                for (int k = s; k < e; k++) {
                    uint2 ed = g_e[k];
                    int rj = (int)ed.x;
                    float u = __uint_as_float(ed.y);
                    int i0 = (int)u;
                    i0 = (i0 > NLUT - 2) ? (NLUT - 2) : i0;
                    float f = u - (float)i0;
                    const uint2* la = (const uint2*)(lut + (size_t)i0 * 64) + lane;
                    uint2 A = la[0];
                    uint2 B = la[32];
                    uint2 X = ((const uint2*)(xin + (size_t)rj * 64))[lane];
                    float2 a0 = __half22float2(*(__half2*)&A.x);
                    float2 a1 = __half22float2(*(__half2*)&A.y);
                    float2 b0 = __half22float2(*(__half2*)&B.x);
                    float2 b1v = __half22float2(*(__half2*)&B.y);
                    float2 x0 = __half22float2(*(__half2*)&X.x);
                    float2 x1 = __half22float2(*(__half2*)&X.y);
                    acc.x = fmaf(fmaf(f, b0.x - a0.x, a0.x), x0.x, acc.x);
                    acc.y = fmaf(fmaf(f, b0.y - a0.y, a0.y), x0.y, acc.y);
                    acc.z = fmaf(fmaf(f, b1v.x - a1.x, a1.x), x1.x, acc.z);
                    acc.w = fmaf(fmaf(f, b1v.y - a1.y, a1.y), x1.y, acc.w);
                }
            }
            __half2 h0 = __floats2half2_rn(acc.x, acc.y);
            __half2 h1 = __floats2half2_rn(acc.z, acc.w);
            sA[nd * SH2 + 2 * lane] = *(unsigned int*)&h0;
            sA[nd * SH2 + 2 * lane + 1] = *(unsigned int*)&h1;
        }
        __syncthreads();

        // GEMM A: h = ssp(agg @ W1 + b1)
        #pragma unroll
        for (int im = 0; im < 2; im++)
            #pragma unroll
            for (int jn = 0; jn < 4; jn++)
                #pragma unroll
                for (int q = 0; q < 4; q++) c[im][jn][q] = 0.0f;
        GEMM_LDSM(c, aRegA, bB);
        #pragma unroll
        for (int q = 0; q < 4; q++) {
            int im = q >> 1, hi = q & 1;
            int row = wm * 32 + im * 16 + hi * 8 + g;
            #pragma unroll
            for (int jn = 0; jn < 4; jn++) {
                int col = wn * 32 + jn * 8 + 2 * r;
                __half2 h = __floats2half2_rn(ssp_fast(c[im][jn][hi * 2 + 0] + sB1[col]),
                                              ssp_fast(c[im][jn][hi * 2 + 1] + sB1[col + 1]));
                sH[row * SH2 + (col >> 1)] = *(unsigned int*)&h;
            }
        }
        __syncthreads();
        for (int i = tid; i < 128 * 64; i += 512)
            sW[(i >> 6) * SH2 + (i & 63)] = W2h[i];
        __syncthreads();

        // GEMM B: v += h @ W2 + b2 ; sA = fp16(v_new)
        #pragma unroll
        for (int im = 0; im < 2; im++)
            #pragma unroll
            for (int jn = 0; jn < 4; jn++)
                #pragma unroll
                for (int q = 0; q < 4; q++) c[im][jn][q] = 0.0f;
        GEMM_LDSM(c, aRegH, bB);
        #pragma unroll
        for (int q = 0; q < 4; q++) {
            int im = q >> 1, hi = q & 1;
            int row = wm * 32 + im * 16 + hi * 8 + g;
            int n = n0 + row;
            if (n >= NN) continue;
            float* vp = g_v + (size_t)n * HC;
            #pragma unroll
            for (int jn = 0; jn < 4; jn++) {
                int col = wn * 32 + jn * 8 + 2 * r;
                float2 old = *(const float2*)(vp + col);
                float2 o;
                o.x = old.x + c[im][jn][hi * 2 + 0] + sB2[col];
                o.y = old.y + c[im][jn][hi * 2 + 1] + sB2[col + 1];
                *(float2*)(vp + col) = o;
                __half2 h = __floats2half2_rn(o.x, o.y);
                sA[row * SH2 + (col >> 1)] = *(unsigned int*)&h;
            }
        }
        if (!linWh) return;
        __syncthreads();
    } else {
        for (int i = tid; i < 128 * 64; i += 512) {
            int row = i >> 6, c2 = i & 63;
            int n = n0 + row;
            float2 vv = (n < NN) ? *(const float2*)(g_v + (size_t)n * HC + 2 * c2)
                                 : make_float2(0.0f, 0.0f);
            __half2 h = __floats2half2_rn(vv.x, vv.y);
            sA[row * SH2 + c2] = *(unsigned int*)&h;
        }
    }

    // GEMM C: x = v_new @ lin -> fp16 to xout
    for (int i = tid; i < 128 * 64; i += 512)
        sW[(i >> 6) * SH2 + (i & 63)] = linWh[i];
    __syncthreads();

    #pragma unroll
    for (int im = 0; im < 2; im++)
        #pragma unroll
        for (int jn = 0; jn < 4; jn++)
            #pragma unroll
            for (int q = 0; q < 4; q++) c[im][jn][q] = 0.0f;
    GEMM_LDSM(c, aRegA, bB);
    #pragma unroll
    for (int q = 0; q < 4; q++) {
        int im = q >> 1, hi = q & 1;
        int row = wm * 32 + im * 16 + hi * 8 + g;
        int n = n0 + row;
        if (n >= NN) continue;
        unsigned int* xp = xout + (size_t)n * 64;
        #pragma unroll
        for (int jn = 0; jn < 4; jn++) {
            int col = wn * 32 + jn * 8 + 2 * r;
            __half2 h = __floats2half2_rn(c[im][jn][hi * 2 + 0], c[im][jn][hi * 2 + 1]);
            xp[col >> 1] = *(unsigned int*)&h;
        }
    }
}

// ---------------- readout ---------------------------------------------------
__global__ void readout_kernel(const int* __restrict__ batch,
                               const float* __restrict__ uW1, const float* __restrict__ ub1,
                               const float* __restrict__ uW2, const float* __restrict__ ub2,
                               float* __restrict__ out)
{
    __shared__ float sv[8][HC];
    int tid = threadIdx.x;
    int w = tid >> 5, l = tid & 31;
    int n0 = blockIdx.x * 8;
    for (int i = tid; i < 8 * HC; i += 256) {
        int n = n0 + (i >> 7);
        sv[i >> 7][i & 127] = (n < NN) ? g_v[(size_t)n * HC + (i & 127)] : 0.0f;
    }
    __syncthreads();
    int n = n0 + w;
    if (n >= NN) return;
    float a0 = 0.0f, a1 = 0.0f;
    #pragma unroll 8
    for (int h = 0; h < HC; h++) {
        float vv = sv[w][h];
        a0 += vv * uW1[h * 64 + l];
        a1 += vv * uW1[h * 64 + l + 32];
    }
    float h0 = ssp_f(a0 + ub1[l]);
    float h1 = ssp_f(a1 + ub1[l + 32]);
    float p = h0 * uW2[l] + h1 * uW2[l + 32];
    #pragma unroll
    for (int o = 16; o; o >>= 1) p += __shfl_down_sync(0xffffffffu, p, o);
    if (l == 0) atomicAdd(&out[batch[n]], p + ub2[0]);
}

// ---------------- launch ----------------------------------------------------
extern "C" void kernel_launch(void* const* d_in, const int* in_sizes, int n_in,
                              void* d_out, int out_size)
{
    const int*   z     = (const int*)d_in[0];
    const float* pos   = (const float*)d_in[1];
    const int*   batch = (const int*)d_in[2];
    const int*   eidx  = (const int*)d_in[3];
    const float* emb   = (const float*)d_in[4];
    const float* lin_W = (const float*)d_in[5];
    const float* mW1   = (const float*)d_in[6];
    const float* mb1   = (const float*)d_in[7];
    const float* mW2   = (const float*)d_in[8];
    const float* mb2   = (const float*)d_in[9];
    const float* vW1   = (const float*)d_in[10];
    const float* vb1   = (const float*)d_in[11];
    const float* vW2   = (const float*)d_in[12];
    const float* vb2   = (const float*)d_in[13];
    const float* uW1   = (const float*)d_in[14];
    const float* ub1   = (const float*)d_in[15];
    const float* uW2   = (const float*)d_in[16];
    const float* ub2   = (const float*)d_in[17];
    float* out = (float*)d_out;

    const int LUT_SMEM = LUT_SMEM_F * (int)sizeof(float);
    cudaFuncSetAttribute(lut_gen_kernel, cudaFuncAttributeMaxDynamicSharedMemorySize, LUT_SMEM);
    cudaFuncSetAttribute(layer_fused_kernel, cudaFuncAttributeMaxDynamicSharedMemorySize, FUSED_SMEM_B);

    init_v_kernel<<<(NN * HC + 255) / 256, 256>>>(z, emb);
    edge_pre_kernel<<<(NE + 255) / 256, 256>>>(pos, eidx);
    scan_part_kernel<<<SNB, SCB>>>();
    scan_emit_kernel<<<SNB, SCB>>>();
    scatter_kernel<<<(NE + 255) / 256, 256>>>(eidx);
    prep_wh_kernel<<<(NLAY * 128 * 64 + 255) / 256, 256>>>(lin_W, vW1, vW2);
    lut_gen_kernel<<<dim3(NLUT / 128, NLAY), 256, LUT_SMEM>>>(mW1, mW2, mb1, mb2);

    const int NODE_GRID = (NN + NT - 1) / NT;   // 391
    unsigned int* lutDev;
    cudaGetSymbolAddress((void**)&lutDev, g_lut_h);
    unsigned int *hLin, *hW1, *hW2, *xh0, *xh1;
    cudaGetSymbolAddress((void**)&hLin, g_hLin);
    cudaGetSymbolAddress((void**)&hW1, g_hW1);
    cudaGetSymbolAddress((void**)&hW2, g_hW2);
    cudaGetSymbolAddress((void**)&xh0, g_xh0);
    cudaGetSymbolAddress((void**)&xh1, g_xh1);

    layer_fused_kernel<<<NODE_GRID, 512, FUSED_SMEM_B>>>(
        nullptr, nullptr, nullptr, nullptr, hLin, nullptr, nullptr, xh0, 0);
    for (int l = 0; l < NLAY; l++) {
        const unsigned int* nextLin = (l + 1 < NLAY) ? (hLin + (size_t)(l + 1) * 8192) : nullptr;
        unsigned int* xin  = (l & 1) ? xh1 : xh0;
        unsigned int* xout = (l & 1) ? xh0 : xh1;
        layer_fused_kernel<<<NODE_GRID, 512, FUSED_SMEM_B>>>(
            hW1 + (size_t)l * 8192, vb1 + (size_t)l * HC,
            hW2 + (size_t)l * 8192, vb2 + (size_t)l * HC,
            nextLin, lutDev + (size_t)l * NLUT * 64, xin, xout, 1);
    }

    zero_out_kernel<<<1, 64>>>(out);
    readout_kernel<<<(NN + 7) / 8, 256>>>(batch, uW1, ub1, uW2, ub2, out);
    (void)in_sizes; (void)n_in; (void)out_size;
}